// round 12
// baseline (speedup 1.0000x reference)
#include <cuda_runtime.h>
#include <cstdint>

// ---------------- problem constants ----------------
#define NROWS 65536          // B*H*W
#define DDIM  128
#define KCODE 4096
#define TM    128            // rows per CTA
#define TN    128            // codes per tile
#define NT    (KCODE / TN)   // 32 tiles
#define HW    4096
#define BATCH 16
#define NELEM (BATCH * DDIM * HW)   // 8388608
#define NCAND 96             // 32 streams x top-3
#define EPSF  3.0f
#define QS    24.0f          // int8 quantization scale
#define SCL   (-1.0f / 288.0f)   // -2 / (QS*QS)

// ---------------- device scratch (no allocs allowed) ----------------
__device__ uint32_t g_z8[NROWS * 32];     // int8(z*24), 128B/row (8 MB)
__device__ uint32_t g_e8[KCODE * 32];     // int8(e*24), 128B/row (512 KB)
__device__ float  g_enorm[KCODE];
__device__ int    g_cand[NROWS * NCAND];
__device__ float  g_candv[NROWS * NCAND];
__device__ int    g_idx[NROWS];
__device__ double g_loss;

// ---------------- smem layout ----------------
#define SA    0                 // A tile 128x128 int8  (16384)
#define SB    16384             // B tiles x2           (32768)
#define SMEM_TOT (16384 + 32768 + 1024)

static __device__ __forceinline__ uint32_t smem_u32(const void* p) {
    uint32_t a;
    asm("{ .reg .u64 t; cvta.to.shared.u64 t, %1; cvt.u32.u64 %0, t; }" : "=r"(a) : "l"(p));
    return a;
}
static __device__ __forceinline__ void ldsm4(uint32_t a[4], uint32_t addr) {
    asm volatile("ldmatrix.sync.aligned.m8n8.x4.shared.b16 {%0,%1,%2,%3}, [%4];"
                 : "=r"(a[0]), "=r"(a[1]), "=r"(a[2]), "=r"(a[3]) : "r"(addr));
}
// s8 x s8 -> s32, m16n8k32 (2x MACs per instruction vs m16n8k16)
static __device__ __forceinline__ void mma16832i(int c[4], const uint32_t a[4],
                                                 uint32_t b0, uint32_t b1) {
    asm volatile("mma.sync.aligned.m16n8k32.row.col.s32.s8.s8.s32 "
                 "{%0,%1,%2,%3}, {%4,%5,%6,%7}, {%8,%9}, {%0,%1,%2,%3};"
                 : "+r"(c[0]), "+r"(c[1]), "+r"(c[2]), "+r"(c[3])
                 : "r"(a[0]), "r"(a[1]), "r"(a[2]), "r"(a[3]), "r"(b0), "r"(b1));
}
#define CP_ASYNC16(dst, src) \
    asm volatile("cp.async.cg.shared.global [%0], [%1], 16;" :: "r"(dst), "l"(src) : "memory")
#define CP_COMMIT() asm volatile("cp.async.commit_group;" ::: "memory")
#define CP_WAIT(N)  asm volatile("cp.async.wait_group %0;" :: "n"(N) : "memory")

static __device__ __forceinline__ int q1(float v) {
    int i = __float2int_rn(v * QS);
    return min(127, max(-127, i));
}
static __device__ __forceinline__ uint32_t q4(float a, float b, float c, float d) {
    return (uint32_t)(q1(a) & 255) | ((uint32_t)(q1(b) & 255) << 8) |
           ((uint32_t)(q1(c) & 255) << 16) | ((uint32_t)(q1(d) & 255) << 24);
}

// ---------------------------------------------------------------------------
// Kernel 0a: z -> int8(z*24); zero loss
// ---------------------------------------------------------------------------
__global__ void zconv_kernel(const float* __restrict__ z) {
    if (blockIdx.x == 0 && threadIdx.x == 0) g_loss = 0.0;
    int i = blockIdx.x * blockDim.x + threadIdx.x;     // < 524288 (16 floats each)
    const float4* z4 = reinterpret_cast<const float4*>(z);
    float4 a = z4[i * 4], b = z4[i * 4 + 1], c = z4[i * 4 + 2], d = z4[i * 4 + 3];
    uint4 o;
    o.x = q4(a.x, a.y, a.z, a.w);
    o.y = q4(b.x, b.y, b.z, b.w);
    o.z = q4(c.x, c.y, c.z, c.w);
    o.w = q4(d.x, d.y, d.z, d.w);
    reinterpret_cast<uint4*>(g_z8)[i] = o;
}

// ---------------------------------------------------------------------------
// Kernel 0b: emb -> int8(e*24) + ||e||^2
// ---------------------------------------------------------------------------
__global__ void econv_kernel(const float* __restrict__ emb) {
    int w = (blockIdx.x * blockDim.x + threadIdx.x) >> 5;   // code
    int l = threadIdx.x & 31;
    float4 v = reinterpret_cast<const float4*>(emb)[w * 32 + l];
    float s = v.x * v.x + v.y * v.y + v.z * v.z + v.w * v.w;
    #pragma unroll
    for (int o = 16; o > 0; o >>= 1) s += __shfl_xor_sync(0xffffffffu, s, o);
    if (l == 0) g_enorm[w] = s;
    g_e8[w * 32 + l] = q4(v.x, v.y, v.z, v.w);
}

// ---------------------------------------------------------------------------
// Kernel 1: int8 mma.sync m16n8k32 GEMM, 512 threads, top-3/stream
// ---------------------------------------------------------------------------
#define TOP3(sl, s, c) do {                                                     \
    if ((s) < bv2[sl]) {                                                        \
        if ((s) < bv0[sl]) { bv2[sl]=bv1[sl]; bi2[sl]=bi1[sl];                  \
                             bv1[sl]=bv0[sl]; bi1[sl]=bi0[sl];                  \
                             bv0[sl]=(s);     bi0[sl]=(c); }                    \
        else if ((s) < bv1[sl]) { bv2[sl]=bv1[sl]; bi2[sl]=bi1[sl];             \
                                  bv1[sl]=(s);     bi1[sl]=(c); }               \
        else { bv2[sl]=(s); bi2[sl]=(c); }                                      \
    } } while (0)

__global__ void __launch_bounds__(512, 1) vq_mma_kernel() {
    extern __shared__ char smraw[];
    uint32_t sb0 = smem_u32(smraw);
    uint32_t base = (sb0 + 1023u) & ~1023u;

    const int tid = threadIdx.x;
    const int wid = tid >> 5;
    const int l   = tid & 31;
    const int wm  = wid >> 3;      // 0..1 : 64-row group
    const int wn  = wid & 7;       // 0..7 : 16-code column
    const int row0 = blockIdx.x * TM;

    // ---- A tile (z rows) + B tile 0; swizzle chunk' = c16 ^ (r&7) ----
    // tiles are 128 rows x 128 B = 1024 16B-chunks; 2 per thread
    {
        const char* srcA = reinterpret_cast<const char*>(g_z8) + (size_t)row0 * 128;
        const char* srcB = reinterpret_cast<const char*>(g_e8);
        #pragma unroll
        for (int i = 0; i < 2; ++i) {
            int f = i * 512 + tid;
            int r = f >> 3, c = f & 7;
            uint32_t so = r * 128 + ((c ^ (r & 7)) << 4);
            CP_ASYNC16(base + SA + so, srcA + r * 128 + c * 16);
            CP_ASYNC16(base + SB + so, srcB + r * 128 + c * 16);
        }
    }
    CP_COMMIT();

    // ---- per-lane fragment addresses ----
    // row-within-16 = ((l>>3)&1)*8 + (l&7); chunk-sel = (l>>4)&1
    uint32_t aab[4];     // A: 4 mf tiles of 16 rows
    uint32_t bab;        // B: 16 codes (wn)
    int asw[4], bsw;
    {
        int arow_l = ((l >> 3) & 1) * 8 + (l & 7);
        #pragma unroll
        for (int mf = 0; mf < 4; ++mf) {
            int r = wm * 64 + mf * 16 + arow_l;
            aab[mf] = base + SA + r * 128;
            asw[mf] = r & 7;
        }
        int brow_l = wn * 16 + ((l >> 3) & 1) * 8 + (l & 7);
        bab = brow_l * 128;
        bsw = brow_l & 7;
    }
    const int csel = (l >> 4) & 1;

    float bv0[8], bv1[8], bv2[8];
    int   bi0[8], bi1[8], bi2[8];
    #pragma unroll
    for (int s = 0; s < 8; ++s) {
        bv0[s] = bv1[s] = bv2[s] = 3.4e38f;
        bi0[s] = bi1[s] = bi2[s] = 0;
    }

    for (int kt = 0; kt < NT; ++kt) {
        __syncthreads();   // everyone done reading the buffer being overwritten
        if (kt + 1 < NT) {
            const char* srcb = reinterpret_cast<const char*>(g_e8) +
                               (size_t)(kt + 1) * TN * 128;
            uint32_t dstb = base + SB + ((kt + 1) & 1) * 16384;
            #pragma unroll
            for (int i = 0; i < 2; ++i) {
                int f = i * 512 + tid;
                int r = f >> 3, c = f & 7;
                CP_ASYNC16(dstb + r * 128 + ((c ^ (r & 7)) << 4), srcb + r * 128 + c * 16);
            }
            CP_COMMIT();
            CP_WAIT(1);
        } else {
            CP_WAIT(0);
        }
        __syncthreads();   // B(kt) (and A at kt=0) visible

        const uint32_t bufb = base + SB + (kt & 1) * 16384;

        int acc[4][2][4];
        #pragma unroll
        for (int mf = 0; mf < 4; ++mf)
            #pragma unroll
            for (int nf = 0; nf < 2; ++nf)
                #pragma unroll
                for (int q = 0; q < 4; ++q) acc[mf][nf][q] = 0;

        #pragma unroll
        for (int ks = 0; ks < 4; ++ks) {
            const int c2 = 2 * ks;        // 16B-chunk base of this 32B K-slice
            uint32_t Af[4][4], Bf[4];
            #pragma unroll
            for (int mf = 0; mf < 4; ++mf)
                ldsm4(Af[mf], aab[mf] + (uint32_t)(((c2 + csel) ^ asw[mf]) << 4));
            ldsm4(Bf, bufb + bab + (uint32_t)(((c2 + csel) ^ bsw) << 4));
            // Bf: [0]=codes0-7 k0-15, [1]=codes8-15 k0-15, [2]=codes0-7 k16-31, [3]=codes8-15 k16-31
            #pragma unroll
            for (int mf = 0; mf < 4; ++mf) {
                mma16832i(acc[mf][0], Af[mf], Bf[0], Bf[2]);
                mma16832i(acc[mf][1], Af[mf], Bf[1], Bf[3]);
            }
        }

        // ---- epilogue: score = enorm + SCL*dot ; top-3 ----
        #pragma unroll
        for (int nf = 0; nf < 2; ++nf) {
            const int cidx = kt * 128 + wn * 16 + nf * 8 + 2 * (l & 3);
            const float2 bp = __ldg(reinterpret_cast<const float2*>(g_enorm + cidx));
            #pragma unroll
            for (int mf = 0; mf < 4; ++mf) {
                float s0 = fmaf((float)acc[mf][nf][0], SCL, bp.x);
                float s1 = fmaf((float)acc[mf][nf][1], SCL, bp.y);
                float s2 = fmaf((float)acc[mf][nf][2], SCL, bp.x);
                float s3 = fmaf((float)acc[mf][nf][3], SCL, bp.y);
                TOP3(mf * 2,     s0, cidx);
                TOP3(mf * 2,     s1, cidx + 1);
                TOP3(mf * 2 + 1, s2, cidx);
                TOP3(mf * 2 + 1, s3, cidx + 1);
            }
        }
    }

    // ---- candidate writeout: 32 stream-positions x 3 per row ----
    #pragma unroll
    for (int s = 0; s < 8; ++s) {
        int row = row0 + wm * 64 + (s >> 1) * 16 + (s & 1) * 8 + (l >> 2);
        int p = wn * 4 + (l & 3);
        int*   d  = g_cand  + (size_t)row * NCAND + p * 3;
        float* dv = g_candv + (size_t)row * NCAND + p * 3;
        d[0]  = bi0[s]; d[1]  = bi1[s]; d[2]  = bi2[s];
        dv[0] = bv0[s]; dv[1] = bv1[s]; dv[2] = bv2[s];
    }
}

// ---------------------------------------------------------------------------
// Kernel 2: filtered exact rescore (warp per row; ~1-2 exact dots per row)
// ---------------------------------------------------------------------------
__global__ void __launch_bounds__(256) rescore_kernel(const float* __restrict__ z,
                                                      const float* __restrict__ emb) {
    __shared__ double wloss[8];
    const int w = threadIdx.x >> 5;
    const int l = threadIdx.x & 31;
    const int r = blockIdx.x * 8 + w;

    float4 zv = reinterpret_cast<const float4*>(z)[(size_t)r * 32 + l];
    float zsq = zv.x * zv.x + zv.y * zv.y + zv.z * zv.z + zv.w * zv.w;
    #pragma unroll
    for (int o = 16; o > 0; o >>= 1) zsq += __shfl_xor_sync(0xffffffffu, zsq, o);

    // lane l owns candidate slots l*3 .. l*3+2
    int   c0 = g_cand [(size_t)r * NCAND + l * 3 + 0];
    int   c1 = g_cand [(size_t)r * NCAND + l * 3 + 1];
    int   c2 = g_cand [(size_t)r * NCAND + l * 3 + 2];
    float v0 = g_candv[(size_t)r * NCAND + l * 3 + 0];
    float v1 = g_candv[(size_t)r * NCAND + l * 3 + 1];
    float v2 = g_candv[(size_t)r * NCAND + l * 3 + 2];

    float m = fminf(v0, fminf(v1, v2));
    #pragma unroll
    for (int o = 16; o > 0; o >>= 1) m = fminf(m, __shfl_xor_sync(0xffffffffu, m, o));
    const float thr = m + EPSF;

    float bestv = 3.4e38f;
    int   besti = 0x7fffffff;
    #pragma unroll
    for (int i = 0; i < 3; ++i) {
        int   ci = (i == 0) ? c0 : (i == 1) ? c1 : c2;
        float vi = (i == 0) ? v0 : (i == 1) ? v1 : v2;
        unsigned msk = __ballot_sync(0xffffffffu, vi <= thr);
        while (msk) {
            int b = __ffs(msk) - 1;
            msk &= msk - 1;
            int c = __shfl_sync(0xffffffffu, ci, b);
            float4 ev = reinterpret_cast<const float4*>(emb)[(size_t)c * 32 + l];
            float d = zv.x * ev.x + zv.y * ev.y + zv.z * ev.z + zv.w * ev.w;
            #pragma unroll
            for (int o = 16; o > 0; o >>= 1) d += __shfl_xor_sync(0xffffffffu, d, o);
            float sc = fmaf(-2.f, d, __ldg(&g_enorm[c]));
            if (sc < bestv || (sc == bestv && c < besti)) { bestv = sc; besti = c; }
        }
    }

    if (l == 0) {
        g_idx[r] = besti;
        wloss[w] = (double)(zsq + bestv);
    }
    __syncthreads();
    if (threadIdx.x == 0) {
        double s = 0.0;
        #pragma unroll
        for (int i = 0; i < 8; ++i) s += wloss[i];
        atomicAdd(&g_loss, s);
    }
}

// ---------------------------------------------------------------------------
// Kernel 3: gather + transpose to [B, D, H, W]
// ---------------------------------------------------------------------------
__global__ void gather_kernel(const float* __restrict__ emb, float* __restrict__ out) {
    int hw = blockIdx.x * blockDim.x + threadIdx.x;  // 0..4095
    int d4 = blockIdx.y;                             // 0..31
    int b  = blockIdx.z;                             // 0..15
    int id = g_idx[b * HW + hw];
    float4 e = __ldg(reinterpret_cast<const float4*>(emb) + (size_t)id * 32 + d4);
    size_t ob = ((size_t)b * DDIM + d4 * 4) * HW + hw;
    out[ob]          = e.x;
    out[ob + HW]     = e.y;
    out[ob + 2 * HW] = e.z;
    out[ob + 3 * HW] = e.w;
}

// ---------------------------------------------------------------------------
// Kernel 4: scalar loss = 1.25 * mean(||z_q - z||^2)
// ---------------------------------------------------------------------------
__global__ void loss_kernel(float* __restrict__ out) {
    out[NELEM] = (float)(1.25 * g_loss / (double)NELEM);
}

// ---------------------------------------------------------------------------
extern "C" void kernel_launch(void* const* d_in, const int* in_sizes, int n_in,
                              void* d_out, int out_size) {
    const float* z   = (const float*)d_in[0];   // [16,64,64,128] fp32
    const float* emb = (const float*)d_in[1];   // [4096,128] fp32
    float* out = (float*)d_out;

    cudaFuncSetAttribute(vq_mma_kernel, cudaFuncAttributeMaxDynamicSharedMemorySize,
                         SMEM_TOT);

    zconv_kernel<<<2048, 256>>>(z);
    econv_kernel<<<512, 256>>>(emb);
    vq_mma_kernel<<<NROWS / TM, 512, SMEM_TOT>>>();
    rescore_kernel<<<NROWS / 8, 256>>>(z, emb);
    gather_kernel<<<dim3(HW / 256, DDIM / 4, BATCH), 256>>>(emb, out);
    if (out_size > NELEM) loss_kernel<<<1, 1>>>(out);
}

// round 13
// speedup vs baseline: 1.0378x; 1.0378x over previous
#include <cuda_runtime.h>
#include <cuda_fp16.h>
#include <cstdint>

// ---------------- problem constants ----------------
#define NROWS 65536          // B*H*W
#define DDIM  128
#define KCODE 4096
#define TM    128            // rows per CTA
#define HW    4096
#define BATCH 16
#define NELEM (BATCH * DDIM * HW)   // 8388608
#define NCAND 64
#define EPSF  1.5f

// code split
#define TNT    44            // tensor tiles of 64 codes
#define TCODES (TNT * 64)    // 2816
#define HSTART TCODES        // hfma codes begin
#define HSPW   640           // codes per hfma stripe (2 stripes)
#define NCH    10            // chunks of 64 codes per stripe

// ---------------- device scratch ----------------
__device__ uint4  g_zh4[NROWS * 16];      // fp16(-2z), 256B/row
__device__ uint4  g_eh4[KCODE * 16];      // fp16(e),   256B/row
__device__ float  g_enorm[KCODE];
__device__ int    g_cand[NROWS * NCAND];
__device__ float  g_candv[NROWS * NCAND];
__device__ int    g_idx[NROWS];
__device__ double g_loss;

// ---------------- smem layout (dynamic, 1KB aligned) ----------------
#define SA   0                 // A tile 128x128 fp16            (32768)
#define SBT  32768             // tensor B tiles x2 (64 codes)   (32768)
#define SEH  65536             // hfma e chunks x2 x 2 stripes   (65536)
#define SMEM_TOT (131072 + 1024)

static __device__ __forceinline__ uint32_t smem_u32(const void* p) {
    uint32_t a;
    asm("{ .reg .u64 t; cvta.to.shared.u64 t, %1; cvt.u32.u64 %0, t; }" : "=r"(a) : "l"(p));
    return a;
}
static __device__ __forceinline__ void ldsm4(uint32_t a[4], uint32_t addr) {
    asm volatile("ldmatrix.sync.aligned.m8n8.x4.shared.b16 {%0,%1,%2,%3}, [%4];"
                 : "=r"(a[0]), "=r"(a[1]), "=r"(a[2]), "=r"(a[3]) : "r"(addr));
}
static __device__ __forceinline__ void mma16816h(uint32_t c[2], const uint32_t a[4],
                                                 uint32_t b0, uint32_t b1) {
    asm volatile("mma.sync.aligned.m16n8k16.row.col.f16.f16.f16.f16 "
                 "{%0,%1}, {%2,%3,%4,%5}, {%6,%7}, {%0,%1};"
                 : "+r"(c[0]), "+r"(c[1])
                 : "r"(a[0]), "r"(a[1]), "r"(a[2]), "r"(a[3]), "r"(b0), "r"(b1));
}
#define CP_ASYNC16(dst, src) \
    asm volatile("cp.async.cg.shared.global [%0], [%1], 16;" :: "r"(dst), "l"(src) : "memory")
#define CP_COMMIT() asm volatile("cp.async.commit_group;" ::: "memory")
#define CP_WAIT(N)  asm volatile("cp.async.wait_group %0;" :: "n"(N) : "memory")
#define BAR(id) asm volatile("bar.sync %0, 256;" :: "r"(id) : "memory")

static __device__ __forceinline__ uint32_t h2pack(float lo, float hi) {
    uint32_t p;
    asm("cvt.rn.f16x2.f32 %0, %1, %2;" : "=r"(p) : "f"(hi), "f"(lo));
    return p;
}

// ---------------------------------------------------------------------------
// Kernel 0a: z -> fp16(-2z); zero loss
// ---------------------------------------------------------------------------
__global__ void zconv_kernel(const float* __restrict__ z) {
    if (blockIdx.x == 0 && threadIdx.x == 0) g_loss = 0.0;
    int i = blockIdx.x * blockDim.x + threadIdx.x;     // < 1048576
    const float4* z4 = reinterpret_cast<const float4*>(z);
    float4 a = z4[i * 2], b = z4[i * 2 + 1];
    uint4 o;
    o.x = h2pack(-2.f * a.x, -2.f * a.y);
    o.y = h2pack(-2.f * a.z, -2.f * a.w);
    o.z = h2pack(-2.f * b.x, -2.f * b.y);
    o.w = h2pack(-2.f * b.z, -2.f * b.w);
    g_zh4[i] = o;
}

// ---------------------------------------------------------------------------
// Kernel 0b: emb -> fp16 + ||e||^2
// ---------------------------------------------------------------------------
__global__ void econv_kernel(const float* __restrict__ emb) {
    int w = (blockIdx.x * blockDim.x + threadIdx.x) >> 5;   // code
    int l = threadIdx.x & 31;
    float4 v = reinterpret_cast<const float4*>(emb)[w * 32 + l];
    float s = v.x * v.x + v.y * v.y + v.z * v.z + v.w * v.w;
    #pragma unroll
    for (int o = 16; o > 0; o >>= 1) s += __shfl_xor_sync(0xffffffffu, s, o);
    if (l == 0) g_enorm[w] = s;
    uint2 p;
    p.x = h2pack(v.x, v.y);
    p.y = h2pack(v.z, v.w);
    reinterpret_cast<uint2*>(g_eh4)[w * 32 + l] = p;
}

// ---------------------------------------------------------------------------
// Kernel 1: dual-pipe — warps 0-7 fp16 HMMA (codes 0..2815),
//                       warps 8-15 HFMA2   (codes 2816..4095)
// ---------------------------------------------------------------------------
#define TOP3(sl, s, c) do {                                                     \
    if ((s) < bv2[sl]) {                                                        \
        if ((s) < bv0[sl]) { bv2[sl]=bv1[sl]; bi2[sl]=bi1[sl];                  \
                             bv1[sl]=bv0[sl]; bi1[sl]=bi0[sl];                  \
                             bv0[sl]=(s);     bi0[sl]=(c); }                    \
        else if ((s) < bv1[sl]) { bv2[sl]=bv1[sl]; bi2[sl]=bi1[sl];             \
                                  bv1[sl]=(s);     bi1[sl]=(c); }               \
        else { bv2[sl]=(s); bi2[sl]=(c); }                                      \
    } } while (0)

__global__ void __launch_bounds__(512, 1) vq_mma_kernel() {
    extern __shared__ char smraw[];
    uint32_t sb0 = smem_u32(smraw);
    uint32_t base = (sb0 + 1023u) & ~1023u;
    char* sm = smraw + (base - sb0);

    const int tid = threadIdx.x;
    const int wid = tid >> 5;
    const int l   = tid & 31;
    const int row0 = blockIdx.x * TM;

    if (wid < 8) {
        // ===================== TENSOR PATH (threads 0-255) =====================
        const int wm = wid >> 2;       // 0..1 : 64-row group
        const int wn = wid & 3;        // 0..3 : 16-code column of 64-code tile

        // A tile (128x256B) + B tile 0 (64x256B), swizzle chunk' = c ^ (r&7)
        {
            const char* srcA = reinterpret_cast<const char*>(g_zh4) + (size_t)row0 * 256;
            const char* srcB = reinterpret_cast<const char*>(g_eh4);
            #pragma unroll
            for (int i = 0; i < 8; ++i) {
                int f = i * 256 + tid;
                int r = f >> 4, c = f & 15;
                CP_ASYNC16(base + SA + r * 256 + ((c ^ (r & 7)) << 4),
                           srcA + r * 256 + c * 16);
            }
            #pragma unroll
            for (int i = 0; i < 4; ++i) {
                int f = i * 256 + tid;
                int r = f >> 4, c = f & 15;
                CP_ASYNC16(base + SBT + r * 256 + ((c ^ (r & 7)) << 4),
                           srcB + r * 256 + c * 16);
            }
        }
        CP_COMMIT();

        // fragment addresses
        uint32_t aab[4], bab;
        {
            int arow_l = ((l >> 3) & 1) * 8 + (l & 7);
            #pragma unroll
            for (int mf = 0; mf < 4; ++mf)
                aab[mf] = base + SA + (wm * 64 + mf * 16 + arow_l) * 256;
            int brow_l = wn * 16 + ((l >> 4) & 1) * 8 + (l & 7);
            bab = brow_l * 256;
        }
        const int asel = (l >> 4) & 1;
        const int bsel = (l >> 3) & 1;
        const int sw   = l & 7;

        float bv0[8], bv1[8], bv2[8];
        int   bi0[8], bi1[8], bi2[8];
        #pragma unroll
        for (int s = 0; s < 8; ++s) {
            bv0[s] = bv1[s] = bv2[s] = 3.4e38f;
            bi0[s] = bi1[s] = bi2[s] = 0;
        }

        for (int kt = 0; kt < TNT; ++kt) {
            BAR(1);   // done reading buffer being overwritten
            if (kt + 1 < TNT) {
                const char* srcb = reinterpret_cast<const char*>(g_eh4) +
                                   (size_t)(kt + 1) * 64 * 256;
                uint32_t dstb = base + SBT + ((kt + 1) & 1) * 16384;
                #pragma unroll
                for (int i = 0; i < 4; ++i) {
                    int f = i * 256 + tid;
                    int r = f >> 4, c = f & 15;
                    CP_ASYNC16(dstb + r * 256 + ((c ^ (r & 7)) << 4),
                               srcb + r * 256 + c * 16);
                }
                CP_COMMIT();
                CP_WAIT(1);
            } else {
                CP_WAIT(0);
            }
            BAR(1);   // B(kt) (and A at kt=0) visible

            const uint32_t bufb = base + SBT + (kt & 1) * 16384;

            uint32_t acc[4][2][2];
            #pragma unroll
            for (int mf = 0; mf < 4; ++mf)
                #pragma unroll
                for (int nf = 0; nf < 2; ++nf) { acc[mf][nf][0] = 0u; acc[mf][nf][1] = 0u; }

            #pragma unroll
            for (int ks = 0; ks < 8; ++ks) {
                const int c2 = 2 * ks;
                uint32_t Af[4][4], Bf[4];
                const uint32_t aoff = (uint32_t)((c2 + asel) ^ sw) << 4;
                const uint32_t boff = (uint32_t)((c2 + bsel) ^ sw) << 4;
                #pragma unroll
                for (int mf = 0; mf < 4; ++mf) ldsm4(Af[mf], aab[mf] + aoff);
                ldsm4(Bf, bufb + bab + boff);
                #pragma unroll
                for (int mf = 0; mf < 4; ++mf) {
                    mma16816h(acc[mf][0], Af[mf], Bf[0], Bf[1]);
                    mma16816h(acc[mf][1], Af[mf], Bf[2], Bf[3]);
                }
            }

            // epilogue: unpack + bias + top-3
            #pragma unroll
            for (int nf = 0; nf < 2; ++nf) {
                const int cidx = kt * 64 + wn * 16 + nf * 8 + 2 * (l & 3);
                const float2 bp = __ldg(reinterpret_cast<const float2*>(g_enorm + cidx));
                #pragma unroll
                for (int mf = 0; mf < 4; ++mf) {
                    float2 lo = __half22float2(*reinterpret_cast<__half2*>(&acc[mf][nf][0]));
                    float2 hi = __half22float2(*reinterpret_cast<__half2*>(&acc[mf][nf][1]));
                    float s0 = lo.x + bp.x;
                    float s1 = lo.y + bp.y;
                    float s2 = hi.x + bp.x;
                    float s3 = hi.y + bp.y;
                    TOP3(mf * 2,     s0, cidx);
                    TOP3(mf * 2,     s1, cidx + 1);
                    TOP3(mf * 2 + 1, s2, cidx);
                    TOP3(mf * 2 + 1, s3, cidx + 1);
                }
            }
        }

        // candidate writeout: 16 streams x 3 -> slots 0..47
        #pragma unroll
        for (int s = 0; s < 8; ++s) {
            int row = row0 + wm * 64 + (s >> 1) * 16 + (s & 1) * 8 + (l >> 2);
            int p = wn * 4 + (l & 3);
            int*   d  = g_cand  + (size_t)row * NCAND + p * 3;
            float* dv = g_candv + (size_t)row * NCAND + p * 3;
            d[0]  = bi0[s]; d[1]  = bi1[s]; d[2]  = bi2[s];
            dv[0] = bv0[s]; dv[1] = bv1[s]; dv[2] = bv2[s];
        }
    } else {
        // ===================== HFMA2 PATH (threads 256-511) =====================
        const int w8 = wid - 8;            // 0..7
        const int rowg = w8 & 3;           // row group (32 rows)
        const int s2 = w8 >> 2;            // stripe 0/1
        const int rowl = rowg * 32 + l;    // 0..127
        const int ht = tid - 256;          // 0..255

        // own z row into registers (64 half2)
        __half2 zr[64];
        {
            const uint4* zp = reinterpret_cast<const uint4*>(g_zh4) +
                              (size_t)(row0 + rowl) * 16;
            #pragma unroll
            for (int j = 0; j < 16; ++j) {
                uint4 v = __ldg(zp + j);
                zr[j*4+0] = *reinterpret_cast<__half2*>(&v.x);
                zr[j*4+1] = *reinterpret_cast<__half2*>(&v.y);
                zr[j*4+2] = *reinterpret_cast<__half2*>(&v.z);
                zr[j*4+3] = *reinterpret_cast<__half2*>(&v.w);
            }
        }

        // preload chunk 0 (both stripes: 128 codes x 256B = 32KB; 128B/thread)
        {
            #pragma unroll
            for (int i = 0; i < 8; ++i) {
                int f = i * 256 + ht;
                int st = f >> 10, r = (f >> 4) & 63, c = f & 15;
                const char* src = reinterpret_cast<const char*>(g_eh4) +
                                  (size_t)(HSTART + st * HSPW + r) * 256 + c * 16;
                CP_ASYNC16(base + SEH + st * 16384 + r * 256 + c * 16, src);
            }
        }
        CP_COMMIT();

        float bv[4]; int bi[4];
        #pragma unroll
        for (int q = 0; q < 4; ++q) { bv[q] = 3.4e38f; bi[q] = 0; }

        for (int ch = 0; ch < NCH; ++ch) {
            if (ch + 1 < NCH) {
                uint32_t dstb = base + SEH + ((ch + 1) & 1) * 32768;
                #pragma unroll
                for (int i = 0; i < 8; ++i) {
                    int f = i * 256 + ht;
                    int st = f >> 10, r = (f >> 4) & 63, c = f & 15;
                    const char* src = reinterpret_cast<const char*>(g_eh4) +
                        (size_t)(HSTART + st * HSPW + (ch + 1) * 64 + r) * 256 + c * 16;
                    CP_ASYNC16(dstb + st * 16384 + r * 256 + c * 16, src);
                }
                CP_COMMIT();
                CP_WAIT(1);
            } else {
                CP_WAIT(0);
            }
            BAR(2);   // chunk ch visible to all hfma threads

            const char* ebase = sm + SEH + (ch & 1) * 32768 + s2 * 16384;
            const int cbase = HSTART + s2 * HSPW + ch * 64;

            #pragma unroll 4
            for (int cl = 0; cl < 64; ++cl) {
                const uint4* ev4 = reinterpret_cast<const uint4*>(ebase + cl * 256);
                __half2 a0 = __floats2half2_rn(0.f, 0.f);
                __half2 a1 = a0;
                #pragma unroll
                for (int j = 0; j < 16; ++j) {
                    uint4 e = ev4[j];
                    a0 = __hfma2(zr[j*4+0], *reinterpret_cast<__half2*>(&e.x), a0);
                    a1 = __hfma2(zr[j*4+1], *reinterpret_cast<__half2*>(&e.y), a1);
                    a0 = __hfma2(zr[j*4+2], *reinterpret_cast<__half2*>(&e.z), a0);
                    a1 = __hfma2(zr[j*4+3], *reinterpret_cast<__half2*>(&e.w), a1);
                }
                float2 f0 = __half22float2(a0);
                float2 f1 = __half22float2(a1);
                float dot = (f0.x + f0.y) + (f1.x + f1.y);
                int code = cbase + cl;
                float sc = dot + __ldg(&g_enorm[code]);
                if (sc < bv[3]) {
                    if (sc < bv[1]) {
                        if (sc < bv[0]) { bv[3]=bv[2];bi[3]=bi[2]; bv[2]=bv[1];bi[2]=bi[1];
                                          bv[1]=bv[0];bi[1]=bi[0]; bv[0]=sc;bi[0]=code; }
                        else            { bv[3]=bv[2];bi[3]=bi[2]; bv[2]=bv[1];bi[2]=bi[1];
                                          bv[1]=sc;bi[1]=code; }
                    } else if (sc < bv[2]) { bv[3]=bv[2];bi[3]=bi[2]; bv[2]=sc;bi[2]=code; }
                    else                   { bv[3]=sc;bi[3]=code; }
                }
            }
            BAR(2);   // done with buffer before next overwrite
        }

        // writeout: slots 48 + s2*4 .. +3 ; stripe-0 warps pad slots 56..63
        {
            int row = row0 + rowl;
            int*   d  = g_cand  + (size_t)row * NCAND + 48 + s2 * 4;
            float* dv = g_candv + (size_t)row * NCAND + 48 + s2 * 4;
            #pragma unroll
            for (int q = 0; q < 4; ++q) { d[q] = bi[q]; dv[q] = bv[q]; }
            if (s2 == 0) {
                int*   dp  = g_cand  + (size_t)row * NCAND + 56;
                float* dvp = g_candv + (size_t)row * NCAND + 56;
                #pragma unroll
                for (int q = 0; q < 8; ++q) { dp[q] = 0; dvp[q] = 3.4e38f; }
            }
        }
    }
}

// ---------------------------------------------------------------------------
// Kernel 2: filtered exact rescore (warp per row; 2 slots per lane)
// ---------------------------------------------------------------------------
__global__ void __launch_bounds__(256) rescore_kernel(const float* __restrict__ z,
                                                      const float* __restrict__ emb) {
    __shared__ double wloss[8];
    const int w = threadIdx.x >> 5;
    const int l = threadIdx.x & 31;
    const int r = blockIdx.x * 8 + w;

    float4 zv = reinterpret_cast<const float4*>(z)[(size_t)r * 32 + l];
    float zsq = zv.x * zv.x + zv.y * zv.y + zv.z * zv.z + zv.w * zv.w;
    #pragma unroll
    for (int o = 16; o > 0; o >>= 1) zsq += __shfl_xor_sync(0xffffffffu, zsq, o);

    int   c0 = g_cand [(size_t)r * NCAND + 2 * l + 0];
    int   c1 = g_cand [(size_t)r * NCAND + 2 * l + 1];
    float v0 = g_candv[(size_t)r * NCAND + 2 * l + 0];
    float v1 = g_candv[(size_t)r * NCAND + 2 * l + 1];

    float m = fminf(v0, v1);
    #pragma unroll
    for (int o = 16; o > 0; o >>= 1) m = fminf(m, __shfl_xor_sync(0xffffffffu, m, o));
    const float thr = m + EPSF;

    float bestv = 3.4e38f;
    int   besti = 0x7fffffff;
    #pragma unroll
    for (int i = 0; i < 2; ++i) {
        int   ci = (i == 0) ? c0 : c1;
        float vi = (i == 0) ? v0 : v1;
        unsigned msk = __ballot_sync(0xffffffffu, vi <= thr);
        while (msk) {
            int b = __ffs(msk) - 1;
            msk &= msk - 1;
            int c = __shfl_sync(0xffffffffu, ci, b);
            float4 ev = reinterpret_cast<const float4*>(emb)[(size_t)c * 32 + l];
            float d = zv.x * ev.x + zv.y * ev.y + zv.z * ev.z + zv.w * ev.w;
            #pragma unroll
            for (int o = 16; o > 0; o >>= 1) d += __shfl_xor_sync(0xffffffffu, d, o);
            float sc = fmaf(-2.f, d, __ldg(&g_enorm[c]));
            if (sc < bestv || (sc == bestv && c < besti)) { bestv = sc; besti = c; }
        }
    }

    if (l == 0) {
        g_idx[r] = besti;
        wloss[w] = (double)(zsq + bestv);
    }
    __syncthreads();
    if (threadIdx.x == 0) {
        double s = 0.0;
        #pragma unroll
        for (int i = 0; i < 8; ++i) s += wloss[i];
        atomicAdd(&g_loss, s);
    }
}

// ---------------------------------------------------------------------------
// Kernel 3: gather + transpose to [B, D, H, W]
// ---------------------------------------------------------------------------
__global__ void gather_kernel(const float* __restrict__ emb, float* __restrict__ out) {
    int hw = blockIdx.x * blockDim.x + threadIdx.x;  // 0..4095
    int d4 = blockIdx.y;                             // 0..31
    int b  = blockIdx.z;                             // 0..15
    int id = g_idx[b * HW + hw];
    float4 e = __ldg(reinterpret_cast<const float4*>(emb) + (size_t)id * 32 + d4);
    size_t ob = ((size_t)b * DDIM + d4 * 4) * HW + hw;
    out[ob]          = e.x;
    out[ob + HW]     = e.y;
    out[ob + 2 * HW] = e.z;
    out[ob + 3 * HW] = e.w;
}

// ---------------------------------------------------------------------------
// Kernel 4: scalar loss = 1.25 * mean(||z_q - z||^2)
// ---------------------------------------------------------------------------
__global__ void loss_kernel(float* __restrict__ out) {
    out[NELEM] = (float)(1.25 * g_loss / (double)NELEM);
}

// ---------------------------------------------------------------------------
extern "C" void kernel_launch(void* const* d_in, const int* in_sizes, int n_in,
                              void* d_out, int out_size) {
    const float* z   = (const float*)d_in[0];   // [16,64,64,128] fp32
    const float* emb = (const float*)d_in[1];   // [4096,128] fp32
    float* out = (float*)d_out;

    cudaFuncSetAttribute(vq_mma_kernel, cudaFuncAttributeMaxDynamicSharedMemorySize,
                         SMEM_TOT);

    zconv_kernel<<<4096, 256>>>(z);
    econv_kernel<<<512, 256>>>(emb);
    vq_mma_kernel<<<NROWS / TM, 512, SMEM_TOT>>>();
    rescore_kernel<<<NROWS / 8, 256>>>(z, emb);
    gather_kernel<<<dim3(HW / 256, DDIM / 4, BATCH), 256>>>(emb, out);
    if (out_size > NELEM) loss_kernel<<<1, 1>>>(out);
}

// round 16
// speedup vs baseline: 1.0656x; 1.0268x over previous
#include <cuda_runtime.h>
#include <cuda_fp16.h>
#include <cstdint>

// ---------------- problem constants ----------------
#define NROWS 65536
#define DDIM  128
#define KCODE 4096
#define TM    128
#define HW    4096
#define BATCH 16
#define NELEM (BATCH * DDIM * HW)
#define NCAND 128            // packed uint32 keys per row
#define EPSF  1.5f

// code split
#define TCT    22            // tensor tiles of 128 codes
#define TCODES (TCT * 128)   // 2816
#define NCH    40            // scalar chunks of 32 codes (1280)

// ---------------- device scratch ----------------
__device__ uint4    g_zh4[NROWS * 16];      // fp16(-2z), 256B/row
__device__ uint4    g_eh4[KCODE * 16];      // fp16(e),   256B/row
__device__ float    g_enorm[KCODE];
__device__ uint32_t g_cand[NROWS * NCAND];  // packed (score|code)
__device__ int      g_idx[NROWS];
__device__ double   g_loss;

// ---------------- smem layout (bytes from 1KB-aligned base) ----------------
#define SA   0          // tensor A tile 128x256B        (32768)
#define SB   32768      // tensor B tiles x2             (65536)
#define ZS   98304      // scalar z: [64 d2][128] half2  (32768)
#define ESC  131072     // scalar e chunks x2: [64][32]  (16384)
#define SMEM_TOT (147456 + 1024)

static __device__ __forceinline__ uint32_t smem_u32(const void* p) {
    uint32_t a;
    asm("{ .reg .u64 t; cvta.to.shared.u64 t, %1; cvt.u32.u64 %0, t; }" : "=r"(a) : "l"(p));
    return a;
}
static __device__ __forceinline__ void ldsm4(uint32_t a[4], uint32_t addr) {
    asm volatile("ldmatrix.sync.aligned.m8n8.x4.shared.b16 {%0,%1,%2,%3}, [%4];"
                 : "=r"(a[0]), "=r"(a[1]), "=r"(a[2]), "=r"(a[3]) : "r"(addr));
}
static __device__ __forceinline__ void mma16816h(uint32_t c[2], const uint32_t a[4],
                                                 uint32_t b0, uint32_t b1) {
    asm volatile("mma.sync.aligned.m16n8k16.row.col.f16.f16.f16.f16 "
                 "{%0,%1}, {%2,%3,%4,%5}, {%6,%7}, {%0,%1};"
                 : "+r"(c[0]), "+r"(c[1])
                 : "r"(a[0]), "r"(a[1]), "r"(a[2]), "r"(a[3]), "r"(b0), "r"(b1));
}
#define CP_ASYNC16(dst, src) \
    asm volatile("cp.async.cg.shared.global [%0], [%1], 16;" :: "r"(dst), "l"(src) : "memory")
#define CP_COMMIT() asm volatile("cp.async.commit_group;" ::: "memory")
#define CP_WAIT(N)  asm volatile("cp.async.wait_group %0;" :: "n"(N) : "memory")
#define BART() asm volatile("bar.sync 1, 512;" ::: "memory")
#define BARS() asm volatile("bar.sync 2, 256;" ::: "memory")
#define LDS128(r, addr) \
    asm volatile("ld.shared.v4.u32 {%0,%1,%2,%3}, [%4];" \
                 : "=r"((r)[0]), "=r"((r)[1]), "=r"((r)[2]), "=r"((r)[3]) : "r"(addr))
#define STS32(addr, v) \
    asm volatile("st.shared.u32 [%0], %1;" :: "r"(addr), "r"(v) : "memory")

static __device__ __forceinline__ uint32_t h2pack(float lo, float hi) {
    uint32_t p;
    asm("cvt.rn.f16x2.f32 %0, %1, %2;" : "=r"(p) : "f"(hi), "f"(lo));
    return p;
}
// ordered-float key: high 20 bits of flipped score | 12-bit code
static __device__ __forceinline__ uint32_t packkey(float s, int c) {
    uint32_t u = __float_as_uint(s);
    u ^= ((uint32_t)((int32_t)u >> 31)) | 0x80000000u;
    return (u & 0xFFFFF000u) | (uint32_t)c;
}
static __device__ __forceinline__ float unpackval(uint32_t k) {
    uint32_t u = k & 0xFFFFF000u;
    u = (u & 0x80000000u) ? (u ^ 0x80000000u) : ~u;
    return __uint_as_float(u);
}
#define PADKEY 0xFF61B000u   // packkey(3e38f, 0)

// ---------------------------------------------------------------------------
// Kernel 0a: z -> fp16(-2z); zero loss
// ---------------------------------------------------------------------------
__global__ void zconv_kernel(const float* __restrict__ z) {
    if (blockIdx.x == 0 && threadIdx.x == 0) g_loss = 0.0;
    int i = blockIdx.x * blockDim.x + threadIdx.x;
    const float4* z4 = reinterpret_cast<const float4*>(z);
    float4 a = z4[i * 2], b = z4[i * 2 + 1];
    uint4 o;
    o.x = h2pack(-2.f * a.x, -2.f * a.y);
    o.y = h2pack(-2.f * a.z, -2.f * a.w);
    o.z = h2pack(-2.f * b.x, -2.f * b.y);
    o.w = h2pack(-2.f * b.z, -2.f * b.w);
    g_zh4[i] = o;
}

// ---------------------------------------------------------------------------
// Kernel 0b: emb -> fp16 + ||e||^2
// ---------------------------------------------------------------------------
__global__ void econv_kernel(const float* __restrict__ emb) {
    int w = (blockIdx.x * blockDim.x + threadIdx.x) >> 5;
    int l = threadIdx.x & 31;
    float4 v = reinterpret_cast<const float4*>(emb)[w * 32 + l];
    float s = v.x * v.x + v.y * v.y + v.z * v.z + v.w * v.w;
    #pragma unroll
    for (int o = 16; o > 0; o >>= 1) s += __shfl_xor_sync(0xffffffffu, s, o);
    if (l == 0) g_enorm[w] = s;
    uint2 p;
    p.x = h2pack(v.x, v.y);
    p.y = h2pack(v.z, v.w);
    reinterpret_cast<uint2*>(g_eh4)[w * 32 + l] = p;
}

// ---------------------------------------------------------------------------
// Kernel 1: dual-pipe. warps 0-15: fp16 HMMA (codes 0..2815)
//           warps 16-23: HFMA2 from smem (codes 2816..4095)
// ---------------------------------------------------------------------------
#define TOP3U(sl, k) do {                                                     \
    if ((k) < kv2[sl]) {                                                      \
        if ((k) < kv0[sl]) { kv2[sl]=kv1[sl]; kv1[sl]=kv0[sl]; kv0[sl]=(k); } \
        else if ((k) < kv1[sl]) { kv2[sl]=kv1[sl]; kv1[sl]=(k); }             \
        else { kv2[sl]=(k); }                                                 \
    } } while (0)

__global__ void __launch_bounds__(768, 1) vq_mma_kernel() {
    extern __shared__ char smraw[];
    uint32_t sb0 = smem_u32(smraw);
    uint32_t base = (sb0 + 1023u) & ~1023u;

    const int tid = threadIdx.x;
    const int wid = tid >> 5;
    const int l   = tid & 31;
    const int row0 = blockIdx.x * TM;

    if (wid < 16) {
        // ==================== TENSOR PATH (threads 0-511) ====================
        const int wm = wid >> 3;     // 0..1
        const int wn = wid & 7;      // 0..7

        {   // A tile + B tile 0; swizzle chunk' = c ^ (r&7)
            const char* srcA = reinterpret_cast<const char*>(g_zh4) + (size_t)row0 * 256;
            const char* srcB = reinterpret_cast<const char*>(g_eh4);
            #pragma unroll
            for (int i = 0; i < 4; ++i) {
                int f = i * 512 + tid;
                int r = f >> 4, c = f & 15;
                uint32_t so = r * 256 + ((c ^ (r & 7)) << 4);
                CP_ASYNC16(base + SA + so, srcA + r * 256 + c * 16);
                CP_ASYNC16(base + SB + so, srcB + r * 256 + c * 16);
            }
        }
        CP_COMMIT();

        uint32_t aab[4], bab;
        {
            int arow_l = ((l >> 3) & 1) * 8 + (l & 7);
            #pragma unroll
            for (int mf = 0; mf < 4; ++mf)
                aab[mf] = base + SA + (wm * 64 + mf * 16 + arow_l) * 256;
            int brow_l = wn * 16 + ((l >> 4) & 1) * 8 + (l & 7);
            bab = brow_l * 256;
        }
        const int asel = (l >> 4) & 1;
        const int bsel = (l >> 3) & 1;
        const int sw   = l & 7;

        uint32_t kv0[8], kv1[8], kv2[8];
        #pragma unroll
        for (int s = 0; s < 8; ++s) { kv0[s] = kv1[s] = kv2[s] = 0xFFFFFFFFu; }

        for (int kt = 0; kt < TCT; ++kt) {
            BART();
            if (kt + 1 < TCT) {
                const char* srcb = reinterpret_cast<const char*>(g_eh4) +
                                   (size_t)(kt + 1) * 128 * 256;
                uint32_t dstb = base + SB + ((kt + 1) & 1) * 32768;
                #pragma unroll
                for (int i = 0; i < 4; ++i) {          // FIXED: full 2048 fragments
                    int f = i * 512 + tid;
                    int r = f >> 4, c = f & 15;
                    CP_ASYNC16(dstb + r * 256 + ((c ^ (r & 7)) << 4),
                               srcb + r * 256 + c * 16);
                }
                CP_COMMIT();
                CP_WAIT(1);
            } else {
                CP_WAIT(0);
            }
            BART();

            const uint32_t bufb = base + SB + (kt & 1) * 32768;

            uint32_t acc[4][2][2];
            #pragma unroll
            for (int mf = 0; mf < 4; ++mf)
                #pragma unroll
                for (int nf = 0; nf < 2; ++nf) { acc[mf][nf][0] = 0u; acc[mf][nf][1] = 0u; }

            #pragma unroll
            for (int ks = 0; ks < 8; ++ks) {
                const int c2 = 2 * ks;
                uint32_t Af[4][4], Bf[4];
                const uint32_t aoff = (uint32_t)((c2 + asel) ^ sw) << 4;
                const uint32_t boff = (uint32_t)((c2 + bsel) ^ sw) << 4;
                #pragma unroll
                for (int mf = 0; mf < 4; ++mf) ldsm4(Af[mf], aab[mf] + aoff);
                ldsm4(Bf, bufb + bab + boff);
                #pragma unroll
                for (int mf = 0; mf < 4; ++mf) {
                    mma16816h(acc[mf][0], Af[mf], Bf[0], Bf[1]);
                    mma16816h(acc[mf][1], Af[mf], Bf[2], Bf[3]);
                }
            }

            #pragma unroll
            for (int nf = 0; nf < 2; ++nf) {
                const int cidx = kt * 128 + wn * 16 + nf * 8 + 2 * (l & 3);
                const float2 bp = __ldg(reinterpret_cast<const float2*>(g_enorm + cidx));
                #pragma unroll
                for (int mf = 0; mf < 4; ++mf) {
                    float2 lo = __half22float2(*reinterpret_cast<__half2*>(&acc[mf][nf][0]));
                    float2 hi = __half22float2(*reinterpret_cast<__half2*>(&acc[mf][nf][1]));
                    uint32_t k0 = packkey(lo.x + bp.x, cidx);
                    uint32_t k1 = packkey(lo.y + bp.y, cidx + 1);
                    uint32_t k2 = packkey(hi.x + bp.x, cidx);
                    uint32_t k3 = packkey(hi.y + bp.y, cidx + 1);
                    TOP3U(mf * 2,     k0);
                    TOP3U(mf * 2,     k1);
                    TOP3U(mf * 2 + 1, k2);
                    TOP3U(mf * 2 + 1, k3);
                }
            }
        }

        // writeout: 32 stream-positions x 3 -> slots 0..95
        #pragma unroll
        for (int s = 0; s < 8; ++s) {
            int row = row0 + wm * 64 + (s >> 1) * 16 + (s & 1) * 8 + (l >> 2);
            int p = wn * 4 + (l & 3);
            uint32_t* d = g_cand + (size_t)row * NCAND + p * 3;
            d[0] = kv0[s]; d[1] = kv1[s]; d[2] = kv2[s];
        }
    } else {
        // ==================== SCALAR HFMA2 PATH (threads 512-767) ====================
        const int ht = tid - 512;        // 0..255
        const int cg = ht & 7;           // code group (4 codes of 32)
        const int rg = ht >> 3;          // row group (4 rows of 128)

        // ---- fill zsc: [d2][row] half2, conflict-free stores ----
        #pragma unroll
        for (int i = 0; i < 8; ++i) {
            int f = i * 256 + ht;
            int r = f & 127, j4 = f >> 7;        // j4 in 0..15
            uint4 v = __ldg(&g_zh4[(size_t)(row0 + r) * 16 + j4]);
            uint32_t a = base + ZS + (((j4 * 4) * 128 + r) << 2);
            STS32(a,            v.x);
            STS32(a + 128 * 4,  v.y);
            STS32(a + 256 * 4,  v.z);
            STS32(a + 384 * 4,  v.w);
        }

        // prefetch esc chunk 0: thread owns code sc = ht&31, d2 group sg = ht>>5
        const int sc = ht & 31;
        const int sg = ht >> 5;          // 0..7
        uint4 p0, p1;
        {
            const uint4* src = &g_eh4[(size_t)(TCODES + sc) * 16 + sg * 2];
            p0 = __ldg(src); p1 = __ldg(src + 1);
        }

        uint32_t kv0[4], kv1[4], kv2[4];
        #pragma unroll
        for (int q = 0; q < 4; ++q) { kv0[q] = kv1[q] = kv2[q] = 0xFFFFFFFFu; }

        const uint32_t zbase = base + ZS + ((4 * rg) << 2);
        for (int ch = 0; ch < NCH; ++ch) {
            // store prefetched chunk into buffer ch&1 (bank = sc -> conflict-free)
            {
                uint32_t a = base + ESC + ((ch & 1) * 2048 + (sg * 8) * 32 + sc) * 4;
                STS32(a,           p0.x);
                STS32(a + 32 * 4,  p0.y);
                STS32(a + 64 * 4,  p0.z);
                STS32(a + 96 * 4,  p0.w);
                STS32(a + 128 * 4, p1.x);
                STS32(a + 160 * 4, p1.y);
                STS32(a + 192 * 4, p1.z);
                STS32(a + 224 * 4, p1.w);
            }
            BARS();
            if (ch + 1 < NCH) {
                const uint4* src = &g_eh4[(size_t)(TCODES + (ch + 1) * 32 + sc) * 16 + sg * 2];
                p0 = __ldg(src); p1 = __ldg(src + 1);
            }

            // compute: 4 rows x 4 codes over 64 d2 steps
            __half2 acc[16];
            #pragma unroll
            for (int q = 0; q < 16; ++q) acc[q] = __floats2half2_rn(0.f, 0.f);

            const uint32_t ebase = base + ESC + ((ch & 1) * 2048 + 4 * cg) * 4;
            #pragma unroll 4
            for (int d2 = 0; d2 < 64; ++d2) {
                uint32_t zr[4], er[4];
                LDS128(zr, zbase + (uint32_t)(d2 * 512));
                LDS128(er, ebase + (uint32_t)(d2 * 128));
                #pragma unroll
                for (int i = 0; i < 4; ++i) {
                    __half2 zh = *reinterpret_cast<__half2*>(&zr[i]);
                    #pragma unroll
                    for (int j = 0; j < 4; ++j)
                        acc[i * 4 + j] = __hfma2(zh, *reinterpret_cast<__half2*>(&er[j]),
                                                 acc[i * 4 + j]);
                }
            }

            // per-chunk epilogue
            const int cb = TCODES + ch * 32 + cg * 4;
            const float4 en = __ldg(reinterpret_cast<const float4*>(g_enorm + cb));
            #pragma unroll
            for (int i = 0; i < 4; ++i) {
                #pragma unroll
                for (int j = 0; j < 4; ++j) {
                    float2 f2 = __half22float2(acc[i * 4 + j]);
                    float e = (j == 0) ? en.x : (j == 1) ? en.y : (j == 2) ? en.z : en.w;
                    uint32_t k = packkey(f2.x + f2.y + e, cb + j);
                    TOP3U(i, k);
                }
            }
            BARS();
        }

        // writeout: row slots 96 + cg*3 (.. 119); cg 0/1 write pads 120..127
        #pragma unroll
        for (int i = 0; i < 4; ++i) {
            int row = row0 + rg * 4 + i;
            uint32_t* d = g_cand + (size_t)row * NCAND + 96 + cg * 3;
            d[0] = kv0[i]; d[1] = kv1[i]; d[2] = kv2[i];
            if (cg < 2) {
                uint32_t* dp = g_cand + (size_t)row * NCAND + 120 + cg * 4;
                dp[0] = PADKEY; dp[1] = PADKEY; dp[2] = PADKEY; dp[3] = PADKEY;
            }
        }
    }
}

// ---------------------------------------------------------------------------
// Kernel 2: filtered exact rescore (warp per row; 4 packed keys per lane)
// ---------------------------------------------------------------------------
__global__ void __launch_bounds__(256) rescore_kernel(const float* __restrict__ z,
                                                      const float* __restrict__ emb) {
    __shared__ double wloss[8];
    const int w = threadIdx.x >> 5;
    const int l = threadIdx.x & 31;
    const int r = blockIdx.x * 8 + w;

    float4 zv = reinterpret_cast<const float4*>(z)[(size_t)r * 32 + l];
    float zsq = zv.x * zv.x + zv.y * zv.y + zv.z * zv.z + zv.w * zv.w;
    #pragma unroll
    for (int o = 16; o > 0; o >>= 1) zsq += __shfl_xor_sync(0xffffffffu, zsq, o);

    uint4 kk = __ldg(reinterpret_cast<const uint4*>(g_cand + (size_t)r * NCAND) + l);
    uint32_t ks[4] = {kk.x, kk.y, kk.z, kk.w};

    float m = 3.4e38f;
    #pragma unroll
    for (int i = 0; i < 4; ++i) m = fminf(m, unpackval(ks[i]));
    #pragma unroll
    for (int o = 16; o > 0; o >>= 1) m = fminf(m, __shfl_xor_sync(0xffffffffu, m, o));
    const float thr = m + EPSF;

    float bestv = 3.4e38f;
    int   besti = 0x7fffffff;
    #pragma unroll
    for (int i = 0; i < 4; ++i) {
        int   ci = (int)(ks[i] & 0xFFFu);
        float vi = unpackval(ks[i]);
        unsigned msk = __ballot_sync(0xffffffffu, vi <= thr);
        while (msk) {
            int b = __ffs(msk) - 1;
            msk &= msk - 1;
            int c = __shfl_sync(0xffffffffu, ci, b);
            float4 ev = reinterpret_cast<const float4*>(emb)[(size_t)c * 32 + l];
            float d = zv.x * ev.x + zv.y * ev.y + zv.z * ev.z + zv.w * ev.w;
            #pragma unroll
            for (int o = 16; o > 0; o >>= 1) d += __shfl_xor_sync(0xffffffffu, d, o);
            float sc = fmaf(-2.f, d, __ldg(&g_enorm[c]));
            if (sc < bestv || (sc == bestv && c < besti)) { bestv = sc; besti = c; }
        }
    }

    if (l == 0) {
        g_idx[r] = besti;
        wloss[w] = (double)(zsq + bestv);
    }
    __syncthreads();
    if (threadIdx.x == 0) {
        double s = 0.0;
        #pragma unroll
        for (int i = 0; i < 8; ++i) s += wloss[i];
        atomicAdd(&g_loss, s);
    }
}

// ---------------------------------------------------------------------------
// Kernel 3: gather + transpose to [B, D, H, W]
// ---------------------------------------------------------------------------
__global__ void gather_kernel(const float* __restrict__ emb, float* __restrict__ out) {
    int hw = blockIdx.x * blockDim.x + threadIdx.x;
    int d4 = blockIdx.y;
    int b  = blockIdx.z;
    int id = g_idx[b * HW + hw];
    float4 e = __ldg(reinterpret_cast<const float4*>(emb) + (size_t)id * 32 + d4);
    size_t ob = ((size_t)b * DDIM + d4 * 4) * HW + hw;
    out[ob]          = e.x;
    out[ob + HW]     = e.y;
    out[ob + 2 * HW] = e.z;
    out[ob + 3 * HW] = e.w;
}

// ---------------------------------------------------------------------------
// Kernel 4: scalar loss
// ---------------------------------------------------------------------------
__global__ void loss_kernel(float* __restrict__ out) {
    out[NELEM] = (float)(1.25 * g_loss / (double)NELEM);
}

// ---------------------------------------------------------------------------
extern "C" void kernel_launch(void* const* d_in, const int* in_sizes, int n_in,
                              void* d_out, int out_size) {
    const float* z   = (const float*)d_in[0];
    const float* emb = (const float*)d_in[1];
    float* out = (float*)d_out;

    cudaFuncSetAttribute(vq_mma_kernel, cudaFuncAttributeMaxDynamicSharedMemorySize,
                         SMEM_TOT);

    zconv_kernel<<<4096, 256>>>(z);
    econv_kernel<<<512, 256>>>(emb);
    vq_mma_kernel<<<NROWS / TM, 768, SMEM_TOT>>>();
    rescore_kernel<<<NROWS / 8, 256>>>(z, emb);
    gather_kernel<<<dim3(HW / 256, DDIM / 4, BATCH), 256>>>(emb, out);
    if (out_size > NELEM) loss_kernel<<<1, 1>>>(out);
}